// round 2
// baseline (speedup 1.0000x reference)
#include <cuda_runtime.h>
#include <cuda_bf16.h>

#define N_NODES 100000
#define N_EDGES 1600000
#define IN_F 128
#define OUT_F 32
#define HEADS 2
#define NHF 64  // HEADS*OUT_F

// ---- scratch (device globals; no allocation) ----
__device__ float g_feat[N_NODES * NHF];   // [N][H][F] = [N][64]
__device__ float g_el[N_NODES * HEADS];
__device__ float g_er[N_NODES * HEADS];
__device__ float g_ex[N_EDGES * HEADS];
__device__ float g_denom[N_NODES * HEADS];
__device__ float g_rst[N_NODES * NHF];
__device__ float g_a[N_NODES];
__device__ float g_b[N_NODES];
__device__ float g_vfold[NHF];
__device__ float g_cfold;

// ---- vectorized L2 reductions (sm_90+) ----
__device__ __forceinline__ void red_add_v2(float* p, float a, float b) {
    asm volatile("red.global.add.v2.f32 [%0], {%1, %2};"
                 :: "l"(p), "f"(a), "f"(b) : "memory");
}
__device__ __forceinline__ void red_add_v4(float* p, float a, float b, float c, float d) {
    asm volatile("red.global.add.v4.f32 [%0], {%1, %2, %3, %4};"
                 :: "l"(p), "f"(a), "f"(b), "f"(c), "f"(d) : "memory");
}

// ---- fold MLP: v = W1@W2, c = b1@W2 + b2 ----
__global__ void k_fold(const float* __restrict__ W1, const float* __restrict__ b1,
                       const float* __restrict__ W2, const float* __restrict__ b2) {
    int t = threadIdx.x;
    if (t < NHF) {
        float v = 0.f;
        #pragma unroll
        for (int j = 0; j < OUT_F; ++j) v += W1[t * OUT_F + j] * W2[j];
        g_vfold[t] = v;
    }
    if (t == 0) {
        float c = b2[0];
        for (int j = 0; j < OUT_F; ++j) c += b1[j] * W2[j];
        g_cfold = c;
    }
}

// ---- feat = x @ W : [100000,128]x[128,64], tiled GEMM BM=64,BN=64,BK=64 ----
__global__ void k_gemm(const float* __restrict__ x, const float* __restrict__ W) {
    __shared__ float Xs[64][68];  // [k][m], padded so float4 rows stay 16B-aligned
    __shared__ float Ws[64][64];  // [k][n]
    const int block_row = blockIdx.x * 64;
    const int t = threadIdx.x;         // 128 threads
    const int tx = t & 15;             // col group: 4 cols
    const int ty = t >> 4;             // row group: 8 rows
    float acc[8][4];
    #pragma unroll
    for (int r = 0; r < 8; ++r)
        #pragma unroll
        for (int c = 0; c < 4; ++c) acc[r][c] = 0.f;

    for (int kt = 0; kt < 2; ++kt) {
        // load X tile (64 rows x 64 k) transposed into Xs[k][m]
        #pragma unroll
        for (int i = t; i < 64 * 16; i += 128) {
            int row = i >> 4, kq = i & 15;
            int gr = block_row + row;
            float4 v = make_float4(0.f, 0.f, 0.f, 0.f);
            if (gr < N_NODES)
                v = *(const float4*)&x[gr * IN_F + kt * 64 + kq * 4];
            Xs[kq * 4 + 0][row] = v.x;
            Xs[kq * 4 + 1][row] = v.y;
            Xs[kq * 4 + 2][row] = v.z;
            Xs[kq * 4 + 3][row] = v.w;
        }
        // load W tile (64 k x 64 n) straight
        #pragma unroll
        for (int i = t; i < 64 * 16; i += 128) {
            int kk = i >> 4, nq = i & 15;
            *(float4*)&Ws[kk][nq * 4] =
                *(const float4*)&W[(kt * 64 + kk) * NHF + nq * 4];
        }
        __syncthreads();
        #pragma unroll 16
        for (int k = 0; k < 64; ++k) {
            float4 wv = *(const float4*)&Ws[k][tx * 4];
            float4 x0 = *(const float4*)&Xs[k][ty * 8];
            float4 x1 = *(const float4*)&Xs[k][ty * 8 + 4];
            float xr[8] = {x0.x, x0.y, x0.z, x0.w, x1.x, x1.y, x1.z, x1.w};
            #pragma unroll
            for (int r = 0; r < 8; ++r) {
                acc[r][0] += xr[r] * wv.x;
                acc[r][1] += xr[r] * wv.y;
                acc[r][2] += xr[r] * wv.z;
                acc[r][3] += xr[r] * wv.w;
            }
        }
        __syncthreads();
    }
    #pragma unroll
    for (int r = 0; r < 8; ++r) {
        int gr = block_row + ty * 8 + r;
        if (gr < N_NODES)
            *(float4*)&g_feat[gr * NHF + tx * 4] =
                make_float4(acc[r][0], acc[r][1], acc[r][2], acc[r][3]);
    }
}

// ---- per-node: el/er attention dots, zero denom & rst. one warp per node ----
__global__ void k_node1(const float* __restrict__ attn_l, const float* __restrict__ attn_r) {
    int warp = (blockIdx.x * blockDim.x + threadIdx.x) >> 5;
    int lane = threadIdx.x & 31;
    if (warp >= N_NODES) return;
    int n = warp;
    float f0 = g_feat[n * NHF + lane];        // head 0
    float f1 = g_feat[n * NHF + 32 + lane];   // head 1
    float el0 = f0 * attn_l[lane];
    float el1 = f1 * attn_l[32 + lane];
    float er0 = f0 * attn_r[lane];
    float er1 = f1 * attn_r[32 + lane];
    #pragma unroll
    for (int o = 16; o > 0; o >>= 1) {
        el0 += __shfl_xor_sync(0xFFFFFFFFu, el0, o);
        el1 += __shfl_xor_sync(0xFFFFFFFFu, el1, o);
        er0 += __shfl_xor_sync(0xFFFFFFFFu, er0, o);
        er1 += __shfl_xor_sync(0xFFFFFFFFu, er1, o);
    }
    if (lane == 0) {
        g_el[n * 2] = el0; g_el[n * 2 + 1] = el1;
        g_er[n * 2] = er0; g_er[n * 2 + 1] = er1;
        *(float2*)&g_denom[n * 2] = make_float2(0.f, 0.f);
    }
    g_rst[n * NHF + lane] = 0.f;
    g_rst[n * NHF + 32 + lane] = 0.f;
}

// ---- per-edge: ex = exp(leakyrelu(el[s]+er[d])); denom[d] += ex ----
__global__ void k_edge_exp(const int* __restrict__ src, const int* __restrict__ dst) {
    int e = blockIdx.x * blockDim.x + threadIdx.x;
    if (e >= N_EDGES) return;
    int s = src[e], d = dst[e];
    float2 els = *(const float2*)&g_el[s * 2];
    float2 erd = *(const float2*)&g_er[d * 2];
    float v0 = els.x + erd.x;
    float v1 = els.y + erd.y;
    v0 = v0 > 0.f ? v0 : 0.2f * v0;
    v1 = v1 > 0.f ? v1 : 0.2f * v1;
    float ex0 = __expf(v0);
    float ex1 = __expf(v1);
    *(float2*)&g_ex[e * 2] = make_float2(ex0, ex1);
    red_add_v2(&g_denom[d * 2], ex0, ex1);
}

// ---- per-(edge,head): rst[d] += alpha * feat[s] via v4 reductions ----
__global__ void k_edge_agg(const int* __restrict__ src, const int* __restrict__ dst) {
    int idx = blockIdx.x * blockDim.x + threadIdx.x;
    if (idx >= N_EDGES * HEADS) return;
    int e = idx >> 1, h = idx & 1;
    int s = src[e], d = dst[e];
    float alpha = g_ex[e * 2 + h] / g_denom[d * 2 + h];
    const float4* fp = (const float4*)&g_feat[s * NHF + h * OUT_F];
    float* rp = &g_rst[d * NHF + h * OUT_F];
    #pragma unroll
    for (int q = 0; q < 8; ++q) {
        float4 v = fp[q];
        red_add_v4(rp + q * 4, alpha * v.x, alpha * v.y, alpha * v.z, alpha * v.w);
    }
}

// ---- per-node: h = relu(mean_heads(rst+bias)); a = h.v[:32], b = h.v[32:] ----
__global__ void k_node2(const float* __restrict__ bias_gat) {
    int warp = (blockIdx.x * blockDim.x + threadIdx.x) >> 5;
    int lane = threadIdx.x & 31;
    if (warp >= N_NODES) return;
    int n = warp;
    float r = (g_rst[n * NHF + lane] + bias_gat[lane] +
               g_rst[n * NHF + 32 + lane] + bias_gat[32 + lane]) * 0.5f;
    float h = fmaxf(r, 0.f);
    float av = h * g_vfold[lane];
    float bv = h * g_vfold[32 + lane];
    #pragma unroll
    for (int o = 16; o > 0; o >>= 1) {
        av += __shfl_xor_sync(0xFFFFFFFFu, av, o);
        bv += __shfl_xor_sync(0xFFFFFFFFu, bv, o);
    }
    if (lane == 0) { g_a[n] = av; g_b[n] = bv; }
}

// ---- per-edge final score ----
__global__ void k_edge_score(const int* __restrict__ src, const int* __restrict__ dst,
                             float* __restrict__ out) {
    int e = blockIdx.x * blockDim.x + threadIdx.x;
    if (e >= N_EDGES) return;
    out[e] = g_a[src[e]] + g_b[dst[e]] + g_cfold;
}

extern "C" void kernel_launch(void* const* d_in, const int* in_sizes, int n_in,
                              void* d_out, int out_size) {
    const float* x       = (const float*)d_in[0];
    const float* W       = (const float*)d_in[1];
    const float* attn_l  = (const float*)d_in[2];
    const float* attn_r  = (const float*)d_in[3];
    const float* bias_gat= (const float*)d_in[4];
    const float* W1      = (const float*)d_in[5];
    const float* b1      = (const float*)d_in[6];
    const float* W2      = (const float*)d_in[7];
    const float* b2      = (const float*)d_in[8];
    const int*   src     = (const int*)d_in[9];
    const int*   dst     = (const int*)d_in[10];
    float* out = (float*)d_out;

    k_fold<<<1, 64>>>(W1, b1, W2, b2);
    k_gemm<<<(N_NODES + 63) / 64, 128>>>(x, W);
    k_node1<<<(N_NODES * 32 + 255) / 256, 256>>>(attn_l, attn_r);
    k_edge_exp<<<(N_EDGES + 255) / 256, 256>>>(src, dst);
    k_edge_agg<<<(N_EDGES * HEADS + 255) / 256, 256>>>(src, dst);
    k_node2<<<(N_NODES * 32 + 255) / 256, 256>>>(bias_gat);
    k_edge_score<<<(N_EDGES + 255) / 256, 256>>>(src, dst, out);
}